// round 11
// baseline (speedup 1.0000x reference)
#include <cuda_runtime.h>
#include <math_constants.h>
#include <string.h>

#define NSEQ 16          // B*H
#define SEQL 1024        // L
#define DIM  64          // D
#define CHK  128         // chunk size
#define NCHK (SEQL/CHK)  // 8
#define D2   128         // 2*DIM
#define NBLK (NSEQ*NCHK) // 128 blocks

__device__ float g_S[NSEQ*NCHK*D2*DIM];
__device__ float g_z[NSEQ*NCHK*D2];
__device__ unsigned int g_bar;   // zero-init; monotone across replays

__device__ __forceinline__ float4 relu4(float4 a){
    a.x = fmaxf(a.x,0.f); a.y = fmaxf(a.y,0.f);
    a.z = fmaxf(a.z,0.f); a.w = fmaxf(a.w,0.f);
    return a;
}
typedef unsigned long long u64c;
__device__ __forceinline__ u64c ffma2(u64c a, u64c b, u64c c){
    u64c d;
    asm("fma.rn.f32x2 %0, %1, %2, %3;" : "=l"(d) : "l"(a), "l"(b), "l"(c));
    return d;
}
__device__ __forceinline__ u64c pk(float x, float y){
    float2 t = make_float2(x, y); u64c r; memcpy(&r, &t, 8); return r;
}
__device__ __forceinline__ u64c dupf(float x){ return pk(x, x); }
__device__ __forceinline__ float2 up(u64c d){
    float2 t; memcpy(&t, &d, 8); return t;
}

__device__ __forceinline__ void grid_barrier() {
    __threadfence();
    __syncthreads();
    if (threadIdx.x == 0) {
        unsigned gen = atomicAdd(&g_bar, 1u);
        unsigned target = (gen / NBLK + 1u) * NBLK;
        while (atomicAdd(&g_bar, 0u) < target) { }
    }
    __syncthreads();
    __threadfence();
}

// ---------------------------------------------------------------------------
// Fused kernel. grid = 128 (one block per (seq, chunk)), block = 512.
// ---------------------------------------------------------------------------
__global__ void __launch_bounds__(512,1)
fused_cos_attn(const float* __restrict__ q, const float* __restrict__ k,
               const float* __restrict__ v, float* __restrict__ out) {
    const int blk = blockIdx.x;
    const int n = blk >> 3, c = blk & 7;
    extern __shared__ float sm[];
    float* qextT = sm;                       // [128 d'][132]
    float* kbuf  = qextT + 128*132;          // kextT [d'][132]; At overlay later
    float* V     = kbuf + 128*132 + 32;      // [128 j][68]
    float* U     = V + 128*68;               // [128 d'][68]
    float* zext  = U + 128*68;               // 128
    float* den   = zext + 128;               // 128
    float* dscr  = den + 128;                // 512
    const int tid = threadIdx.x;
    const size_t base = ((size_t)n*SEQL + (size_t)c*CHK)*DIM;
    const float4* q4 = (const float4*)(q + base);
    const float4* k4 = (const float4*)(k + base);
    const float4* v4 = (const float4*)(v + base);

    // ---- Stage q,k,v: qextT/kextT transposed [d'][j], V row-major ----
    {
        const int j = tid & 127;
        const float ang = 1.5707963268f * (float)(c*CHK + j + 1) * (1.f/(float)SEQL);
        const float s = __sinf(ang), cc = __cosf(ang);
        #pragma unroll
        for (int it = 0; it < 4; it++) {
            int f = (tid >> 7) + 4*it;       // 0..15
            float4 qq = relu4(q4[j*16 + f]);
            float4 kk = relu4(k4[j*16 + f]);
            float4 vv = relu4(v4[j*16 + f]);
            int d = 4*f;
            qextT[(d+0)*132 + j] = qq.x*s;  qextT[(d+64)*132 + j] = qq.x*cc;
            qextT[(d+1)*132 + j] = qq.y*s;  qextT[(d+65)*132 + j] = qq.y*cc;
            qextT[(d+2)*132 + j] = qq.z*s;  qextT[(d+66)*132 + j] = qq.z*cc;
            qextT[(d+3)*132 + j] = qq.w*s;  qextT[(d+67)*132 + j] = qq.w*cc;
            kbuf[(d+0)*132 + j] = kk.x*s;   kbuf[(d+64)*132 + j] = kk.x*cc;
            kbuf[(d+1)*132 + j] = kk.y*s;   kbuf[(d+65)*132 + j] = kk.y*cc;
            kbuf[(d+2)*132 + j] = kk.z*s;   kbuf[(d+66)*132 + j] = kk.z*cc;
            kbuf[(d+3)*132 + j] = kk.w*s;   kbuf[(d+67)*132 + j] = kk.w*cc;
            *(float4*)&V[j*68 + d] = vv;
        }
    }
    __syncthreads();

    // ---- z (threads 128..255) concurrent with chunk GEMM (threads 0..127) ----
    if (tid >= 128 && tid < 256) {
        const int dp = tid - 128;
        float zz = 0.f;
        #pragma unroll 8
        for (int j = 0; j < CHK; j++) zz += kbuf[dp*132 + j];
        g_z[blk*D2 + dp] = zz;
    }

    // ---- Chunk-state GEMM: S[d'][m] = sum_j kextT[d'][j]*V[j][m]; 8x8 tiles --
    if (tid < 128) {
        const int td = tid >> 3, tm8 = tid & 7;   // 16 x 8
        const int d0 = td*8, m0 = tm8*2;          // m0 in float4 units
        const float4* V4 = (const float4*)V;
        u64c acc[8][4];                           // [d' row][m-pair]
        #pragma unroll
        for (int r = 0; r < 8; r++)
            #pragma unroll
            for (int mp = 0; mp < 4; mp++) acc[r][mp] = pk(0.f,0.f);

        #pragma unroll 2
        for (int j = 0; j < CHK; j++) {
            float kr[8];
            #pragma unroll
            for (int r = 0; r < 8; r++) kr[r] = kbuf[(d0+r)*132 + j];
            float4 v0 = V4[j*17 + m0];
            float4 v1 = V4[j*17 + m0 + 1];
            u64c vp[4] = { pk(v0.x,v0.y), pk(v0.z,v0.w),
                           pk(v1.x,v1.y), pk(v1.z,v1.w) };
            #pragma unroll
            for (int r = 0; r < 8; r++) {
                u64c kd = dupf(kr[r]);
                #pragma unroll
                for (int mp = 0; mp < 4; mp++)
                    acc[r][mp] = ffma2(kd, vp[mp], acc[r][mp]);
            }
        }
        float4* oS = (float4*)(g_S + (size_t)blk*D2*DIM);
        #pragma unroll
        for (int r = 0; r < 8; r++) {
            float2 a0 = up(acc[r][0]), a1 = up(acc[r][1]);
            float2 a2 = up(acc[r][2]), a3 = up(acc[r][3]);
            oS[(d0+r)*16 + m0    ] = make_float4(a0.x,a0.y,a1.x,a1.y);
            oS[(d0+r)*16 + m0 + 1] = make_float4(a2.x,a2.y,a3.x,a3.y);
        }
    }

    grid_barrier();

    // ---- Prefix state U = sum of chunks 0..c-1 ----
    {
        float4 ua[4];
        #pragma unroll
        for (int it = 0; it < 4; it++) ua[it] = make_float4(0.f,0.f,0.f,0.f);
        const float4* gSn = (const float4*)(g_S + (size_t)(n*NCHK)*D2*DIM);
        for (int cc = 0; cc < c; cc++) {
            const float4* p = gSn + (size_t)cc*2048;
            #pragma unroll
            for (int it = 0; it < 4; it++) {
                float4 t = p[tid + 512*it];
                ua[it].x += t.x; ua[it].y += t.y; ua[it].z += t.z; ua[it].w += t.w;
            }
        }
        float4* U4w = (float4*)U;
        #pragma unroll
        for (int it = 0; it < 4; it++) {
            int i4 = tid + 512*it;
            U4w[(i4 >> 4)*17 + (i4 & 15)] = ua[it];
        }
        if (tid < D2) {
            float zz = 0.f;
            for (int cc = 0; cc < c; cc++) zz += g_z[(n*NCHK + cc)*D2 + tid];
            zext[tid] = zz;
        }
    }
    __syncthreads();

    const float4* qT4 = (const float4*)qextT;
    const float4* kT4 = (const float4*)kbuf;

    // ---- Phase A: A[l][j] = sum_d' qext[d'][l]*kext[d'][j]; 8l x 8j tiles ----
    // 256 threads (8 warps). warp: wl = wid&3 (l in [32wl,32wl+32)),
    // wj2 = wid>>2 (j in [64wj2, 64wj2+64)). Skip wj2=1 && wl<2 (pure j>l).
    const int wid = tid >> 5, lane = tid & 31;
    const int wl = wid & 3, wj2 = wid >> 2;
    const int tl = wl*4 + (lane >> 3);       // 0..15, l0 = 8*tl
    const int tj = wj2*8 + (lane & 7);       // 0..15, j0 = 8*tj
    const int l0 = tl*8, j0 = tj*8;
    const bool activeA = (tid < 256) && !(wj2 == 1 && wl < 2);
    u64c a2[8][4];                            // [jj][l-pair]
    #pragma unroll
    for (int jj = 0; jj < 8; jj++)
        #pragma unroll
        for (int lp = 0; lp < 4; lp++) a2[jj][lp] = pk(0.f,0.f);

    if (activeA) {
        #pragma unroll 2
        for (int dp = 0; dp < D2; dp++) {
            float4 qa = qT4[dp*33 + 2*tl];
            float4 qb = qT4[dp*33 + 2*tl + 1];
            float4 kA = kT4[dp*33 + 2*tj];
            float4 kB = kT4[dp*33 + 2*tj + 1];
            u64c qp[4] = { pk(qa.x,qa.y), pk(qa.z,qa.w),
                           pk(qb.x,qb.y), pk(qb.z,qb.w) };
            float kv[8] = {kA.x,kA.y,kA.z,kA.w, kB.x,kB.y,kB.z,kB.w};
            #pragma unroll
            for (int jj = 0; jj < 8; jj++) {
                u64c kd = dupf(kv[jj]);
                #pragma unroll
                for (int lp = 0; lp < 4; lp++)
                    a2[jj][lp] = ffma2(kd, qp[lp], a2[jj][lp]);
            }
        }
    }
    __syncthreads();

    // Masked transposed store At[j][l] into kbuf, XOR-swizzled float4 groups.
    float4* At4 = (float4*)kbuf;
    if (activeA) {
        #pragma unroll
        for (int jj = 0; jj < 8; jj++) {
            int j = j0 + jj;
            int swz = (j >> 3) & 7;
            float w[8];
            #pragma unroll
            for (int lp = 0; lp < 4; lp++) {
                float2 p = up(a2[jj][lp]);
                w[2*lp]   = (j <= l0 + 2*lp)     ? p.x : 0.f;
                w[2*lp+1] = (j <= l0 + 2*lp + 1) ? p.y : 0.f;
            }
            At4[j*33 + ((2*tl)   ^ swz)] = make_float4(w[0],w[1],w[2],w[3]);
            At4[j*33 + ((2*tl+1) ^ swz)] = make_float4(w[4],w[5],w[6],w[7]);
        }
    }
    __syncthreads();

    // ---- Denominator (512 threads, 4 partials per l) ----
    {
        const int l = tid >> 2, part = tid & 3;
        float dd = 0.f;
        const int jlo = part*32;
        const int jhi = min(jlo + 32, l + 1);
        for (int j = jlo; j < jhi; j++) {
            int swz = (j >> 3) & 7;
            dd += kbuf[j*132 + 4*((l>>2) ^ swz) + (l & 3)];
        }
        #pragma unroll 8
        for (int dp = jlo; dp < jlo + 32; dp++)
            dd = fmaf(qextT[dp*132 + l], zext[dp], dd);
        dscr[tid] = dd;
    }
    __syncthreads();
    if (tid < CHK)
        den[tid] = fmaxf(dscr[4*tid] + dscr[4*tid+1] + dscr[4*tid+2] + dscr[4*tid+3], 1e-6f);
    __syncthreads();

    // ---- Phase B: out = A*V + qext*U; 8l x 8m tiles on 128 threads ----
    if (tid < 128) {
        const int tlB = tid >> 3, tmB = tid & 7;   // 16 x 8
        const int lB0 = tlB*8, m0 = tmB*2;          // m0 in float4 units
        u64c o2[4][4];                              // [l-pair][m-pair]
        #pragma unroll
        for (int lp = 0; lp < 4; lp++)
            #pragma unroll
            for (int mp = 0; mp < 4; mp++) o2[lp][mp] = pk(0.f,0.f);

        const float4* V4c = (const float4*)V;
        const float4* U4c = (const float4*)U;

        const int jmax = lB0 + 8;                   // A[l][j]=0 for j>l
        #pragma unroll 2
        for (int j = 0; j < jmax; j++) {
            int swz = (j >> 3) & 7;
            float4 A0 = At4[j*33 + ((2*tlB)   ^ swz)];
            float4 A1 = At4[j*33 + ((2*tlB+1) ^ swz)];
            float4 v0 = V4c[j*17 + m0];
            float4 v1 = V4c[j*17 + m0 + 1];
            u64c ap[4] = { pk(A0.x,A0.y), pk(A0.z,A0.w),
                           pk(A1.x,A1.y), pk(A1.z,A1.w) };
            float vf[8] = {v0.x,v0.y,v0.z,v0.w, v1.x,v1.y,v1.z,v1.w};
            #pragma unroll
            for (int mp = 0; mp < 4; mp++) {
                u64c vd0 = dupf(vf[2*mp]);
                u64c vd1 = dupf(vf[2*mp+1]);
                // interleave: o2[lp][mp] pairs over l, columns 2mp,2mp+1 handled
                // as two FFMA2 per (lp): accumulate column-major in pairs
                o2[0][mp] = ffma2(ap[0], pk(vf[2*mp], vf[2*mp]), o2[0][mp]);
                (void)vd0; (void)vd1;
                o2[1][mp] = ffma2(ap[1], pk(vf[2*mp], vf[2*mp]), o2[1][mp]);
                o2[2][mp] = ffma2(ap[2], pk(vf[2*mp+1], vf[2*mp+1]), o2[2][mp]);
                o2[3][mp] = ffma2(ap[3], pk(vf[2*mp+1], vf[2*mp+1]), o2[3][mp]);
            }
        }
        // NOTE on o2 layout: o2[0..1][mp] = l-pairs (0,1),(2,3) x column 2mp
        //                    o2[2..3][mp] = l-pairs (0,1),(2,3) x column 2mp+1
        // where ap[0..3] = l-pairs (0,1),(2,3),(4,5),(6,7). Rebind:
        // o2[0][mp]: l(0,1) col 2mp ; o2[1][mp]: l(2,3) col 2mp
        // o2[2][mp]: l(4,5) col 2mp+1 ; o2[3][mp]: l(6,7) col 2mp+1  -- WRONG.
        // To keep it correct, redo accumulation below for the remaining halves.
        // (We instead use a clean full structure: see o3.)
        u64c o3[4][4];                              // [l-pair][m col subset]
        #pragma unroll
        for (int lp = 0; lp < 4; lp++)
            #pragma unroll
            for (int mp = 0; mp < 4; mp++) o3[lp][mp] = pk(0.f,0.f);
        #pragma unroll 2
        for (int j = 0; j < jmax; j++) {
            int swz = (j >> 3) & 7;
            float4 A0 = At4[j*33 + ((2*tlB)   ^ swz)];
            float4 A1 = At4[j*33 + ((2*tlB+1) ^ swz)];
            float4 v1 = V4c[j*17 + m0 + 1];
            u64c ap[4] = { pk(A0.x,A0.y), pk(A0.z,A0.w),
                           pk(A1.x,A1.y), pk(A1.z,A1.w) };
            float vf2[4] = {v1.x,v1.y,v1.z,v1.w};
            #pragma unroll
            for (int mp = 0; mp < 4; mp++) {
                u64c vd = dupf(vf2[mp]);
                #pragma unroll
                for (int lp = 0; lp < 4; lp++)
                    o3[lp][mp] = ffma2(ap[lp], vd, o3[lp][mp]);
            }
        }
        // Recompute first half cleanly into o2 (cols of v0)
        #pragma unroll
        for (int lp = 0; lp < 4; lp++)
            #pragma unroll
            for (int mp = 0; mp < 4; mp++) o2[lp][mp] = pk(0.f,0.f);
        #pragma unroll 2
        for (int j = 0; j < jmax; j++) {
            int swz = (j >> 3) & 7;
            float4 A0 = At4[j*33 + ((2*tlB)   ^ swz)];
            float4 A1 = At4[j*33 + ((2*tlB+1) ^ swz)];
            float4 v0 = V4c[j*17 + m0];
            u64c ap[4] = { pk(A0.x,A0.y), pk(A0.z,A0.w),
                           pk(A1.x,A1.y), pk(A1.z,A1.w) };
            float vf1[4] = {v0.x,v0.y,v0.z,v0.w};
            #pragma unroll
            for (int mp = 0; mp < 4; mp++) {
                u64c vd = dupf(vf1[mp]);
                #pragma unroll
                for (int lp = 0; lp < 4; lp++)
                    o2[lp][mp] = ffma2(ap[lp], vd, o2[lp][mp]);
            }
        }
        // qext * U term
        #pragma unroll 2
        for (int dp = 0; dp < D2; dp++) {
            float4 qa = qT4[dp*33 + 2*tlB];
            float4 qb = qT4[dp*33 + 2*tlB + 1];
            float4 u0 = U4c[dp*17 + m0];
            float4 u1 = U4c[dp*17 + m0 + 1];
            u64c qp[4] = { pk(qa.x,qa.y), pk(qa.z,qa.w),
                           pk(qb.x,qb.y), pk(qb.z,qb.w) };
            float uf1[4] = {u0.x,u0.y,u0.z,u0.w};
            float uf2[4] = {u1.x,u1.y,u1.z,u1.w};
            #pragma unroll
            for (int mp = 0; mp < 4; mp++) {
                u64c ud0 = dupf(uf1[mp]);
                u64c ud1 = dupf(uf2[mp]);
                #pragma unroll
                for (int lp = 0; lp < 4; lp++) {
                    o2[lp][mp] = ffma2(qp[lp], ud0, o2[lp][mp]);
                    o3[lp][mp] = ffma2(qp[lp], ud1, o3[lp][mp]);
                }
            }
        }

        float* ob = out + base;
        #pragma unroll
        for (int lp = 0; lp < 4; lp++) {
            float2 c0 = up(o2[lp][0]), c1 = up(o2[lp][1]);
            float2 c2 = up(o2[lp][2]), c3 = up(o2[lp][3]);
            float2 d0_ = up(o3[lp][0]), d1_ = up(o3[lp][1]);
            float2 d2_ = up(o3[lp][2]), d3_ = up(o3[lp][3]);
            float r0 = 1.f / den[lB0 + 2*lp];
            float r1 = 1.f / den[lB0 + 2*lp + 1];
            float* r0p = &ob[(lB0+2*lp)*64 + m0*4];
            float* r1p = &ob[(lB0+2*lp+1)*64 + m0*4];
            *(float4*)&r0p[0] = make_float4(c0.x*r0, c1.x*r0, c2.x*r0, c3.x*r0);
            *(float4*)&r0p[4] = make_float4(d0_.x*r0, d1_.x*r0, d2_.x*r0, d3_.x*r0);
            *(float4*)&r1p[0] = make_float4(c0.y*r1, c1.y*r1, c2.y*r1, c3.y*r1);
            *(float4*)&r1p[4] = make_float4(d0_.y*r1, d1_.y*r1, d2_.y*r1, d3_.y*r1);
        }
    }
}

extern "C" void kernel_launch(void* const* d_in, const int* in_sizes, int n_in,
                              void* d_out, int out_size) {
    const float* q = (const float*)d_in[0];
    const float* k = (const float*)d_in[1];
    const float* v = (const float*)d_in[2];
    float* out = (float*)d_out;

    const int smem = (128*132 + 128*132 + 32 + 2*128*68 + 128 + 128 + 512) * 4; // 208,000 B
    cudaFuncSetAttribute(fused_cos_attn, cudaFuncAttributeMaxDynamicSharedMemorySize, smem);
    fused_cos_attn<<<NBLK, 512, smem>>>(q, k, v, out);
}

// round 12
// speedup vs baseline: 1.2862x; 1.2862x over previous
#include <cuda_runtime.h>
#include <math_constants.h>
#include <string.h>

#define NSEQ 16          // B*H
#define SEQL 1024        // L
#define DIM  64          // D
#define CHK  128         // chunk size
#define NCHK (SEQL/CHK)  // 8
#define D2   128         // 2*DIM
#define NBLK (NSEQ*NCHK) // 128 blocks

__device__ float g_S[NSEQ*NCHK*D2*DIM];
__device__ float g_z[NSEQ*NCHK*D2];
__device__ unsigned int g_bar;   // zero-init; monotone across replays

__device__ __forceinline__ float4 relu4(float4 a){
    a.x = fmaxf(a.x,0.f); a.y = fmaxf(a.y,0.f);
    a.z = fmaxf(a.z,0.f); a.w = fmaxf(a.w,0.f);
    return a;
}
typedef unsigned long long u64c;
__device__ __forceinline__ u64c ffma2(u64c a, u64c b, u64c c){
    u64c d;
    asm("fma.rn.f32x2 %0, %1, %2, %3;" : "=l"(d) : "l"(a), "l"(b), "l"(c));
    return d;
}
__device__ __forceinline__ u64c pk(float x, float y){
    float2 t = make_float2(x, y); u64c r; memcpy(&r, &t, 8); return r;
}
__device__ __forceinline__ u64c dupf(float x){ return pk(x, x); }
__device__ __forceinline__ float2 up(u64c d){
    float2 t; memcpy(&t, &d, 8); return t;
}

__device__ __forceinline__ void grid_barrier() {
    __threadfence();
    __syncthreads();
    if (threadIdx.x == 0) {
        unsigned gen = atomicAdd(&g_bar, 1u);
        unsigned target = (gen / NBLK + 1u) * NBLK;
        while (atomicAdd(&g_bar, 0u) < target) { }
    }
    __syncthreads();
    __threadfence();
}

// ---------------------------------------------------------------------------
// Fused kernel. grid = 128 (one block per (seq, chunk)), block = 512.
// ---------------------------------------------------------------------------
__global__ void __launch_bounds__(512,1)
fused_cos_attn(const float* __restrict__ q, const float* __restrict__ k,
               const float* __restrict__ v, float* __restrict__ out) {
    const int blk = blockIdx.x;
    const int n = blk >> 3, c = blk & 7;
    extern __shared__ float sm[];
    float* qextT = sm;                       // [128 d'][132]
    float* kbuf  = qextT + 128*132;          // kextT [d'][132]; At overlay later
    float* V     = kbuf + 128*132 + 32;      // [128 j][68]
    float* U     = V + 128*68;               // [128 d'][68]
    float* zext  = U + 128*68;               // 128
    float* den   = zext + 128;               // 128
    float* dscr  = den + 128;                // 512
    const int tid = threadIdx.x;
    const size_t base = ((size_t)n*SEQL + (size_t)c*CHK)*DIM;
    const float4* q4 = (const float4*)(q + base);
    const float4* k4 = (const float4*)(k + base);
    const float4* v4 = (const float4*)(v + base);

    // ---- Stage q,k,v: qextT/kextT transposed [d'][j], V row-major ----
    {
        const int j = tid & 127;
        const float ang = 1.5707963268f * (float)(c*CHK + j + 1) * (1.f/(float)SEQL);
        const float s = __sinf(ang), cc = __cosf(ang);
        #pragma unroll
        for (int it = 0; it < 4; it++) {
            int f = (tid >> 7) + 4*it;       // 0..15
            float4 qq = relu4(q4[j*16 + f]);
            float4 kk = relu4(k4[j*16 + f]);
            float4 vv = relu4(v4[j*16 + f]);
            int d = 4*f;
            qextT[(d+0)*132 + j] = qq.x*s;  qextT[(d+64)*132 + j] = qq.x*cc;
            qextT[(d+1)*132 + j] = qq.y*s;  qextT[(d+65)*132 + j] = qq.y*cc;
            qextT[(d+2)*132 + j] = qq.z*s;  qextT[(d+66)*132 + j] = qq.z*cc;
            qextT[(d+3)*132 + j] = qq.w*s;  qextT[(d+67)*132 + j] = qq.w*cc;
            kbuf[(d+0)*132 + j] = kk.x*s;   kbuf[(d+64)*132 + j] = kk.x*cc;
            kbuf[(d+1)*132 + j] = kk.y*s;   kbuf[(d+65)*132 + j] = kk.y*cc;
            kbuf[(d+2)*132 + j] = kk.z*s;   kbuf[(d+66)*132 + j] = kk.z*cc;
            kbuf[(d+3)*132 + j] = kk.w*s;   kbuf[(d+67)*132 + j] = kk.w*cc;
            *(float4*)&V[j*68 + d] = vv;
        }
    }
    __syncthreads();

    // ---- z[d'] = sum_j kextT[d'][j] ----
    if (tid < D2) {
        float zz = 0.f;
        #pragma unroll 8
        for (int j = 0; j < CHK; j++) zz += kbuf[tid*132 + j];
        g_z[blk*D2 + tid] = zz;
    }

    // ---- Chunk-state GEMM: S[d'][m] = sum_j kextT[d'][j]*V[j][m] (4d' x 4m) --
    {
        const int td = tid >> 4, tm = tid & 15;     // 32 x 16
        const int d0 = td*4;
        const float4* V4 = (const float4*)V;
        u64c acc2[2][4];
        #pragma unroll
        for (int r = 0; r < 2; r++)
            #pragma unroll
            for (int m = 0; m < 4; m++) acc2[r][m] = pk(0.f,0.f);

        #pragma unroll 2
        for (int jb = 0; jb < CHK; jb += 4) {
            float kra[4][4];
            #pragma unroll
            for (int r = 0; r < 4; r++)
                *(float4*)kra[r] = *(const float4*)&kbuf[(d0+r)*132 + jb];
            float4 vv[4];
            #pragma unroll
            for (int i = 0; i < 4; i++) vv[i] = V4[(jb+i)*17 + tm];
            #pragma unroll
            for (int i = 0; i < 4; i++) {
                u64c kp0 = pk(kra[0][i], kra[1][i]);
                u64c kp1 = pk(kra[2][i], kra[3][i]);
                float vf[4] = {vv[i].x, vv[i].y, vv[i].z, vv[i].w};
                #pragma unroll
                for (int m = 0; m < 4; m++) {
                    u64c vd = dupf(vf[m]);
                    acc2[0][m] = ffma2(kp0, vd, acc2[0][m]);
                    acc2[1][m] = ffma2(kp1, vd, acc2[1][m]);
                }
            }
        }
        float4* oS = (float4*)(g_S + (size_t)blk*D2*DIM);
        #pragma unroll
        for (int r = 0; r < 2; r++) {
            float2 a0 = up(acc2[r][0]);
            float2 a1 = up(acc2[r][1]);
            float2 a2 = up(acc2[r][2]);
            float2 a3 = up(acc2[r][3]);
            oS[(d0+2*r)*16   + tm] = make_float4(a0.x,a1.x,a2.x,a3.x);
            oS[(d0+2*r+1)*16 + tm] = make_float4(a0.y,a1.y,a2.y,a3.y);
        }
    }

    grid_barrier();

    const float4* qT4 = (const float4*)qextT;
    const float4* kT4 = (const float4*)kbuf;

    // ---- Phase A (wid 0..9) concurrent with U prefix load (wid 10..15) ----
    // Triangular warp remap: active pairs (wl,wj), wj<=wl, packed into wid 0..9
    // -> SMSP loads 3/3/2/2 (balanced).
    const int wid = tid >> 5, lane = tid & 31;
    const int wl = (wid >= 1) + (wid >= 3) + (wid >= 6);
    const int wj = wid - (wl*(wl+1))/2;
    const int tl = wl*4 + (lane >> 3);       // 0..15, l-tile of 8
    const int tj = wj*8 + (lane & 7);        // 0..31, j-tile of 4
    const int l0 = tl*8, j0 = tj*4;
    const bool activeA = (wid < 10);
    u64c a2[4][4];                            // [jj][l-pair]
    #pragma unroll
    for (int jj = 0; jj < 4; jj++)
        #pragma unroll
        for (int lp = 0; lp < 4; lp++) a2[jj][lp] = pk(0.f,0.f);

    if (activeA) {
        #pragma unroll 4
        for (int dp = 0; dp < D2; dp++) {
            float4 qa = qT4[dp*33 + 2*tl];
            float4 qb = qT4[dp*33 + 2*tl + 1];
            float4 kA = kT4[dp*33 + tj];
            u64c qp[4] = { pk(qa.x,qa.y), pk(qa.z,qa.w),
                           pk(qb.x,qb.y), pk(qb.z,qb.w) };
            float kv[4] = {kA.x,kA.y,kA.z,kA.w};
            #pragma unroll
            for (int jj = 0; jj < 4; jj++) {
                u64c kd = dupf(kv[jj]);
                #pragma unroll
                for (int lp = 0; lp < 4; lp++)
                    a2[jj][lp] = ffma2(kd, qp[lp], a2[jj][lp]);
            }
        }
    } else {
        // wid 10..15 (192 threads): U = sum of chunks 0..c-1, zext likewise.
        const int t = tid - 320;             // 0..191
        const float4* gSn = (const float4*)(g_S + (size_t)(n*NCHK)*D2*DIM);
        float4* U4w = (float4*)U;
        for (int i4 = t; i4 < 2048; i4 += 192) {
            float4 acc = make_float4(0.f,0.f,0.f,0.f);
            for (int cc = 0; cc < c; cc++) {
                float4 x = gSn[(size_t)cc*2048 + i4];
                acc.x += x.x; acc.y += x.y; acc.z += x.z; acc.w += x.w;
            }
            U4w[(i4 >> 4)*17 + (i4 & 15)] = acc;
        }
        if (t < D2) {
            float zz = 0.f;
            for (int cc = 0; cc < c; cc++) zz += g_z[(n*NCHK + cc)*D2 + t];
            zext[t] = zz;
        }
    }
    __syncthreads();

    // Masked transposed store At[j][l] (active warps only; upper-triangle
    // warp tiles are never read downstream). XOR-swizzled float4 groups.
    float4* At4 = (float4*)kbuf;
    if (activeA) {
        #pragma unroll
        for (int jj = 0; jj < 4; jj++) {
            int j = j0 + jj;
            int swz = (j >> 3) & 7;
            float w[8];
            #pragma unroll
            for (int lp = 0; lp < 4; lp++) {
                float2 p = up(a2[jj][lp]);
                w[2*lp]   = (j <= l0 + 2*lp)     ? p.x : 0.f;
                w[2*lp+1] = (j <= l0 + 2*lp + 1) ? p.y : 0.f;
            }
            At4[j*33 + ((2*tl)   ^ swz)] = make_float4(w[0],w[1],w[2],w[3]);
            At4[j*33 + ((2*tl+1) ^ swz)] = make_float4(w[4],w[5],w[6],w[7]);
        }
    }
    __syncthreads();

    // ---- Denominator (512 threads, 4 partials per l) ----
    {
        const int l = tid >> 2, part = tid & 3;
        float dd = 0.f;
        const int jlo = part*32;
        const int jhi = min(jlo + 32, l + 1);
        for (int j = jlo; j < jhi; j++) {
            int swz = (j >> 3) & 7;
            dd += kbuf[j*132 + 4*((l>>2) ^ swz) + (l & 3)];
        }
        #pragma unroll 8
        for (int dp = jlo; dp < jlo + 32; dp++)
            dd = fmaf(qextT[dp*132 + l], zext[dp], dd);
        dscr[tid] = dd;
    }
    __syncthreads();
    if (tid < CHK)
        den[tid] = fmaxf(dscr[4*tid] + dscr[4*tid+1] + dscr[4*tid+2] + dscr[4*tid+3], 1e-6f);
    __syncthreads();

    // ---- Phase B: out = A*V + qext*U; 4l x 4m tiles on 512 threads ----
    const int tlB = tid >> 4, tmB = tid & 15;
    const int lB0 = tlB*4, mB0 = tmB*4;
    u64c o2[2][4];
    #pragma unroll
    for (int lp = 0; lp < 2; lp++)
        #pragma unroll
        for (int mm = 0; mm < 4; mm++) o2[lp][mm] = pk(0.f,0.f);

    const float4* V4c = (const float4*)V;
    const float4* U4c = (const float4*)U;

    const int jmax = lB0 + 4;                 // A[l][j]=0 for j>l
    #pragma unroll 4
    for (int j = 0; j < jmax; j++) {
        int swz = (j >> 3) & 7;
        float4 A0 = At4[j*33 + (tlB ^ swz)];
        float4 vv = V4c[j*17 + tmB];
        u64c ap0 = pk(A0.x,A0.y), ap1 = pk(A0.z,A0.w);
        float vf[4] = {vv.x,vv.y,vv.z,vv.w};
        #pragma unroll
        for (int mm = 0; mm < 4; mm++) {
            u64c vd = dupf(vf[mm]);
            o2[0][mm] = ffma2(ap0, vd, o2[0][mm]);
            o2[1][mm] = ffma2(ap1, vd, o2[1][mm]);
        }
    }
    #pragma unroll 4
    for (int dp = 0; dp < D2; dp++) {
        float4 qa = qT4[dp*33 + tlB];
        float4 uu = U4c[dp*17 + tmB];
        u64c qp0 = pk(qa.x,qa.y), qp1 = pk(qa.z,qa.w);
        float uf[4] = {uu.x,uu.y,uu.z,uu.w};
        #pragma unroll
        for (int mm = 0; mm < 4; mm++) {
            u64c ud = dupf(uf[mm]);
            o2[0][mm] = ffma2(qp0, ud, o2[0][mm]);
            o2[1][mm] = ffma2(qp1, ud, o2[1][mm]);
        }
    }

    float* ob = out + base;
    {
        float2 p00 = up(o2[0][0]), p01 = up(o2[0][1]);
        float2 p02 = up(o2[0][2]), p03 = up(o2[0][3]);
        float2 p10 = up(o2[1][0]), p11 = up(o2[1][1]);
        float2 p12 = up(o2[1][2]), p13 = up(o2[1][3]);
        float r0 = 1.f/den[lB0],   r1 = 1.f/den[lB0+1];
        float r2 = 1.f/den[lB0+2], r3 = 1.f/den[lB0+3];
        *(float4*)&ob[(lB0+0)*64 + mB0] = make_float4(p00.x*r0, p01.x*r0, p02.x*r0, p03.x*r0);
        *(float4*)&ob[(lB0+1)*64 + mB0] = make_float4(p00.y*r1, p01.y*r1, p02.y*r1, p03.y*r1);
        *(float4*)&ob[(lB0+2)*64 + mB0] = make_float4(p10.x*r2, p11.x*r2, p12.x*r2, p13.x*r2);
        *(float4*)&ob[(lB0+3)*64 + mB0] = make_float4(p10.y*r3, p11.y*r3, p12.y*r3, p13.y*r3);
    }
}

extern "C" void kernel_launch(void* const* d_in, const int* in_sizes, int n_in,
                              void* d_out, int out_size) {
    const float* q = (const float*)d_in[0];
    const float* k = (const float*)d_in[1];
    const float* v = (const float*)d_in[2];
    float* out = (float*)d_out;

    const int smem = (128*132 + 128*132 + 32 + 2*128*68 + 128 + 128 + 512) * 4; // 208,000 B
    cudaFuncSetAttribute(fused_cos_attn, cudaFuncAttributeMaxDynamicSharedMemorySize, smem);
    fused_cos_attn<<<NBLK, 512, smem>>>(q, k, v, out);
}

// round 13
// speedup vs baseline: 1.2939x; 1.0059x over previous
#include <cuda_runtime.h>
#include <math_constants.h>
#include <string.h>

#define NSEQ 16          // B*H
#define SEQL 1024        // L
#define DIM  64          // D
#define CHK  128         // chunk size
#define NCHK (SEQL/CHK)  // 8
#define D2   128         // 2*DIM
#define NBLK (NSEQ*NCHK) // 128 blocks

__device__ float g_S[NSEQ*NCHK*D2*DIM];
__device__ float g_z[NSEQ*NCHK*D2];
__device__ unsigned int g_bar;   // zero-init; monotone across replays

__device__ __forceinline__ float4 relu4(float4 a){
    a.x = fmaxf(a.x,0.f); a.y = fmaxf(a.y,0.f);
    a.z = fmaxf(a.z,0.f); a.w = fmaxf(a.w,0.f);
    return a;
}
typedef unsigned long long u64c;
__device__ __forceinline__ u64c ffma2(u64c a, u64c b, u64c c){
    u64c d;
    asm("fma.rn.f32x2 %0, %1, %2, %3;" : "=l"(d) : "l"(a), "l"(b), "l"(c));
    return d;
}
__device__ __forceinline__ u64c pk(float x, float y){
    float2 t = make_float2(x, y); u64c r; memcpy(&r, &t, 8); return r;
}
__device__ __forceinline__ u64c dupf(float x){ return pk(x, x); }
__device__ __forceinline__ float2 up(u64c d){
    float2 t; memcpy(&t, &d, 8); return t;
}

__device__ __forceinline__ void grid_barrier() {
    __threadfence();
    __syncthreads();
    if (threadIdx.x == 0) {
        unsigned gen = atomicAdd(&g_bar, 1u);
        unsigned target = (gen / NBLK + 1u) * NBLK;
        while (atomicAdd(&g_bar, 0u) < target) { }
    }
    __syncthreads();
    __threadfence();
}

// ---------------------------------------------------------------------------
// Fused kernel. grid = 128 (one block per (seq, chunk)), block = 512.
// ---------------------------------------------------------------------------
__global__ void __launch_bounds__(512,1)
fused_cos_attn(const float* __restrict__ q, const float* __restrict__ k,
               const float* __restrict__ v, float* __restrict__ out) {
    const int blk = blockIdx.x;
    const int n = blk >> 3, c = blk & 7;
    extern __shared__ float sm[];
    float* qT  = sm;                     // [64 d][132]  plain relu(q) transposed
    float* kT  = qT + 64*132;            // [64 d][132]  plain relu(k) transposed; obuf overlay
    float* kx  = kT + 64*132;            // [128 d'][132] kextT (sin/cos scaled); At overlay
    float* V   = kx + 128*132 + 32;      // [128 j][68]
    float* U   = V + 128*68;             // [128 d'][68]  prefix state
    float* sth = U + 128*68;             // 128
    float* cth = sth + 128;              // 128
    float* zext= cth + 128;              // 128 (prefix z, extended)
    float* den = zext + 128;             // 128
    float* dscr= den + 128;              // 512
    const int tid = threadIdx.x;
    const size_t base = ((size_t)n*SEQL + (size_t)c*CHK)*DIM;
    const float4* q4 = (const float4*)(q + base);
    const float4* k4 = (const float4*)(k + base);
    const float4* v4 = (const float4*)(v + base);

    // ---- Stage: qT/kT plain transposed, kx extended transposed, V row-major --
    {
        const int j = tid & 127;
        const float ang = 1.5707963268f * (float)(c*CHK + j + 1) * (1.f/(float)SEQL);
        const float s = __sinf(ang), cc = __cosf(ang);
        if (tid < 128) { sth[j] = s; cth[j] = cc; }
        #pragma unroll
        for (int it = 0; it < 4; it++) {
            int f = (tid >> 7) + 4*it;       // 0..15
            float4 qq = relu4(q4[j*16 + f]);
            float4 kk = relu4(k4[j*16 + f]);
            float4 vv = relu4(v4[j*16 + f]);
            int d = 4*f;
            qT[(d+0)*132 + j] = qq.x; qT[(d+1)*132 + j] = qq.y;
            qT[(d+2)*132 + j] = qq.z; qT[(d+3)*132 + j] = qq.w;
            kT[(d+0)*132 + j] = kk.x; kT[(d+1)*132 + j] = kk.y;
            kT[(d+2)*132 + j] = kk.z; kT[(d+3)*132 + j] = kk.w;
            kx[(d+0)*132 + j] = kk.x*s;  kx[(d+64)*132 + j] = kk.x*cc;
            kx[(d+1)*132 + j] = kk.y*s;  kx[(d+65)*132 + j] = kk.y*cc;
            kx[(d+2)*132 + j] = kk.z*s;  kx[(d+66)*132 + j] = kk.z*cc;
            kx[(d+3)*132 + j] = kk.w*s;  kx[(d+67)*132 + j] = kk.w*cc;
            *(float4*)&V[j*68 + d] = vv;
        }
    }
    __syncthreads();

    // ---- z[d'] (threads 256..383) concurrent with chunk GEMM (0..255) ----
    if (tid >= 256 && tid < 384) {
        const int dp = tid - 256;
        const float4* row4 = (const float4*)&kx[dp*132];
        float zz = 0.f;
        #pragma unroll 8
        for (int jf = 0; jf < 32; jf++) {
            float4 t = row4[jf];
            zz += t.x + t.y + t.z + t.w;
        }
        g_z[blk*D2 + dp] = zz;
    }

    // ---- Chunk-state GEMM: S[d'][m] = sum_j kx[d'][j]*V[j][m]
    //      8 d' (interleaved by 16) x 4 m per thread, 256 threads ----
    if (tid < 256) {
        const int td = tid & 15, tm = tid >> 4;   // d-interleave slot, m-group
        const float4* V4 = (const float4*)V;
        u64c acc[4][4];                           // [d-pair][m]
        #pragma unroll
        for (int rp = 0; rp < 4; rp++)
            #pragma unroll
            for (int m = 0; m < 4; m++) acc[rp][m] = pk(0.f,0.f);

        #pragma unroll 2
        for (int jb = 0; jb < CHK; jb += 4) {
            float krf[8][4];
            #pragma unroll
            for (int r = 0; r < 8; r++)
                *(float4*)krf[r] = *(const float4*)&kx[(td + 16*r)*132 + jb];
            float4 vv[4];
            #pragma unroll
            for (int i = 0; i < 4; i++) vv[i] = V4[(jb+i)*17 + tm];
            #pragma unroll
            for (int i = 0; i < 4; i++) {
                float vf[4] = {vv[i].x, vv[i].y, vv[i].z, vv[i].w};
                u64c kp[4];
                #pragma unroll
                for (int rp = 0; rp < 4; rp++)
                    kp[rp] = pk(krf[2*rp][i], krf[2*rp+1][i]);
                #pragma unroll
                for (int m = 0; m < 4; m++) {
                    u64c vd = dupf(vf[m]);
                    #pragma unroll
                    for (int rp = 0; rp < 4; rp++)
                        acc[rp][m] = ffma2(kp[rp], vd, acc[rp][m]);
                }
            }
        }
        float4* oS = (float4*)(g_S + (size_t)blk*D2*DIM);
        #pragma unroll
        for (int rp = 0; rp < 4; rp++) {
            float2 a0 = up(acc[rp][0]), a1 = up(acc[rp][1]);
            float2 a2 = up(acc[rp][2]), a3 = up(acc[rp][3]);
            oS[(td + 16*(2*rp  ))*16 + tm] = make_float4(a0.x,a1.x,a2.x,a3.x);
            oS[(td + 16*(2*rp+1))*16 + tm] = make_float4(a0.y,a1.y,a2.y,a3.y);
        }
    }

    grid_barrier();

    const float4* qT4 = (const float4*)qT;
    const float4* kT4 = (const float4*)kT;

    // ---- Phase A (wid 0..9, K=64 plain) || U prefix load (wid 10..15) ----
    const int wid = tid >> 5, lane = tid & 31;
    const int wl = (wid >= 1) + (wid >= 3) + (wid >= 6);
    const int wj = wid - (wl*(wl+1))/2;
    const int tl = wl*4 + (lane >> 3);       // 0..15, l-tile of 8
    const int tj = wj*8 + (lane & 7);        // 0..31, j-tile of 4
    const int l0 = tl*8, j0 = tj*4;
    const bool activeA = (wid < 10);
    u64c a2[4][4];                            // [jj][l-pair]
    #pragma unroll
    for (int jj = 0; jj < 4; jj++)
        #pragma unroll
        for (int lp = 0; lp < 4; lp++) a2[jj][lp] = pk(0.f,0.f);

    if (activeA) {
        #pragma unroll 4
        for (int dp = 0; dp < 64; dp++) {
            float4 qa = qT4[dp*33 + 2*tl];
            float4 qb = qT4[dp*33 + 2*tl + 1];
            float4 kA = kT4[dp*33 + tj];
            u64c qp[4] = { pk(qa.x,qa.y), pk(qa.z,qa.w),
                           pk(qb.x,qb.y), pk(qb.z,qb.w) };
            float kv[4] = {kA.x,kA.y,kA.z,kA.w};
            #pragma unroll
            for (int jj = 0; jj < 4; jj++) {
                u64c kd = dupf(kv[jj]);
                #pragma unroll
                for (int lp = 0; lp < 4; lp++)
                    a2[jj][lp] = ffma2(kd, qp[lp], a2[jj][lp]);
            }
        }
    } else {
        // wid 10..15 (192 threads): U = sum of chunks 0..c-1, zext prefix.
        const int t = tid - 320;
        const float4* gSn = (const float4*)(g_S + (size_t)(n*NCHK)*D2*DIM);
        float4* U4w = (float4*)U;
        for (int i4 = t; i4 < 2048; i4 += 192) {
            float4 acc = make_float4(0.f,0.f,0.f,0.f);
            for (int cc = 0; cc < c; cc++) {
                float4 x = gSn[(size_t)cc*2048 + i4];
                acc.x += x.x; acc.y += x.y; acc.z += x.z; acc.w += x.w;
            }
            U4w[(i4 >> 4)*17 + (i4 & 15)] = acc;
        }
        if (t < D2) {
            float zz = 0.f;
            for (int cc = 0; cc < c; cc++) zz += g_z[(n*NCHK + cc)*D2 + t];
            zext[t] = zz;
        }
    }
    __syncthreads();

    // ---- At store with cos-identity epilogue (XOR-swizzled float4 groups) ----
    float4* At4 = (float4*)kx;
    if (activeA) {
        float slv[8], clv[8];
        #pragma unroll
        for (int i = 0; i < 8; i++) { slv[i] = sth[l0+i]; clv[i] = cth[l0+i]; }
        #pragma unroll
        for (int jj = 0; jj < 4; jj++) {
            int j = j0 + jj;
            int swz = (j >> 3) & 7;
            float sj = sth[j], cj = cth[j];
            float w[8];
            #pragma unroll
            for (int lp = 0; lp < 4; lp++) {
                float2 p = up(a2[jj][lp]);
                float f0 = fmaf(clv[2*lp],   cj, slv[2*lp]*sj);
                float f1 = fmaf(clv[2*lp+1], cj, slv[2*lp+1]*sj);
                w[2*lp]   = (j <= l0 + 2*lp)     ? p.x * f0 : 0.f;
                w[2*lp+1] = (j <= l0 + 2*lp + 1) ? p.y * f1 : 0.f;
            }
            At4[j*33 + ((2*tl)   ^ swz)] = make_float4(w[0],w[1],w[2],w[3]);
            At4[j*33 + ((2*tl+1) ^ swz)] = make_float4(w[4],w[5],w[6],w[7]);
        }
    }
    __syncthreads();

    // ---- Denominator (512 threads, 4 partials per l) ----
    {
        const int l = tid >> 2, part = tid & 3;
        float dd = 0.f;
        const int jlo = part*32;
        const int jhi = min(jlo + 32, l + 1);
        for (int j = jlo; j < jhi; j++) {
            int swz = (j >> 3) & 7;
            dd += kx[j*132 + 4*((l>>2) ^ swz) + (l & 3)];
        }
        const float sl_ = sth[l], cl_ = cth[l];
        const int dlo = part*16;
        #pragma unroll 8
        for (int d = dlo; d < dlo + 16; d++)
            dd = fmaf(qT[d*132 + l], fmaf(sl_, zext[d], cl_*zext[d+64]), dd);
        dscr[tid] = dd;
    }
    __syncthreads();
    if (tid < CHK)
        den[tid] = fmaxf(dscr[4*tid] + dscr[4*tid+1] + dscr[4*tid+2] + dscr[4*tid+3], 1e-6f);
    __syncthreads();

    // ---- Phase B: warps 0..7 AV (8l x 4m) || warps 8..15 qU (8l x 4m) ----
    const int tt = tid & 255;
    const int tlB = tt >> 4, tmB = tt & 15;
    const int lB0 = tlB*8, m0 = tmB*4;
    u64c oav[4][4];                           // AV acc; live only on tid<256 path
    if (tid < 256) {
        #pragma unroll
        for (int lp = 0; lp < 4; lp++)
            #pragma unroll
            for (int m = 0; m < 4; m++) oav[lp][m] = pk(0.f,0.f);
        const float4* V4c = (const float4*)V;
        const int jmax = lB0 + 8;             // A[l][j]=0 for j>l
        #pragma unroll 4
        for (int j = 0; j < jmax; j++) {
            int swz = (j >> 3) & 7;
            float4 A0 = At4[j*33 + ((2*tlB)   ^ swz)];
            float4 A1 = At4[j*33 + ((2*tlB+1) ^ swz)];
            float4 vv = V4c[j*17 + tmB];
            u64c ap[4] = { pk(A0.x,A0.y), pk(A0.z,A0.w),
                           pk(A1.x,A1.y), pk(A1.z,A1.w) };
            float vf[4] = {vv.x,vv.y,vv.z,vv.w};
            #pragma unroll
            for (int m = 0; m < 4; m++) {
                u64c vd = dupf(vf[m]);
                #pragma unroll
                for (int lp = 0; lp < 4; lp++)
                    oav[lp][m] = ffma2(ap[lp], vd, oav[lp][m]);
            }
        }
    } else {
        const float4* U4c = (const float4*)U;
        u64c aS[4][4], aC[4][4];
        #pragma unroll
        for (int lp = 0; lp < 4; lp++)
            #pragma unroll
            for (int m = 0; m < 4; m++) { aS[lp][m] = pk(0.f,0.f); aC[lp][m] = pk(0.f,0.f); }
        #pragma unroll 4
        for (int d = 0; d < 64; d++) {
            float4 qa = qT4[d*33 + 2*tlB];
            float4 qb = qT4[d*33 + 2*tlB + 1];
            float4 u0 = U4c[d*17 + tmB];
            float4 u1 = U4c[(d+64)*17 + tmB];
            u64c qp[4] = { pk(qa.x,qa.y), pk(qa.z,qa.w),
                           pk(qb.x,qb.y), pk(qb.z,qb.w) };
            float usf[4] = {u0.x,u0.y,u0.z,u0.w};
            float ucf[4] = {u1.x,u1.y,u1.z,u1.w};
            #pragma unroll
            for (int m = 0; m < 4; m++) {
                u64c us = dupf(usf[m]);
                u64c uc = dupf(ucf[m]);
                #pragma unroll
                for (int lp = 0; lp < 4; lp++) {
                    aS[lp][m] = ffma2(qp[lp], us, aS[lp][m]);
                    aC[lp][m] = ffma2(qp[lp], uc, aC[lp][m]);
                }
            }
        }
        // epilogue: obuf[l][m] = sl*(q.Us) + cl*(q.Uc); obuf overlays kT (stride 64)
        float4* ob4 = (float4*)kT;
        #pragma unroll
        for (int lp = 0; lp < 4; lp++) {
            int le = lB0 + 2*lp, lo_ = le + 1;
            float sE = sth[le], cE = cth[le];
            float sO = sth[lo_], cO = cth[lo_];
            float2 s0 = up(aS[lp][0]), s1 = up(aS[lp][1]);
            float2 s2 = up(aS[lp][2]), s3 = up(aS[lp][3]);
            float2 c0 = up(aC[lp][0]), c1 = up(aC[lp][1]);
            float2 c2 = up(aC[lp][2]), c3 = up(aC[lp][3]);
            ob4[le*16 + tmB]  = make_float4(fmaf(sE,s0.x,cE*c0.x), fmaf(sE,s1.x,cE*c1.x),
                                            fmaf(sE,s2.x,cE*c2.x), fmaf(sE,s3.x,cE*c3.x));
            ob4[lo_*16 + tmB] = make_float4(fmaf(sO,s0.y,cO*c0.y), fmaf(sO,s1.y,cO*c1.y),
                                            fmaf(sO,s2.y,cO*c2.y), fmaf(sO,s3.y,cO*c3.y));
        }
    }
    __syncthreads();

    // ---- Combine + divide + store (warps 0..7) ----
    if (tid < 256) {
        const float4* ob4 = (const float4*)kT;
        float* ob = out + base;
        #pragma unroll
        for (int lp = 0; lp < 4; lp++) {
            int le = lB0 + 2*lp;
            float r0 = 1.f / den[le];
            float r1 = 1.f / den[le+1];
            float4 qv0 = ob4[le*16 + tmB];
            float4 qv1 = ob4[(le+1)*16 + tmB];
            float2 p0 = up(oav[lp][0]), p1 = up(oav[lp][1]);
            float2 p2 = up(oav[lp][2]), p3 = up(oav[lp][3]);
            *(float4*)&ob[le*64 + m0] =
                make_float4((p0.x+qv0.x)*r0, (p1.x+qv0.y)*r0, (p2.x+qv0.z)*r0, (p3.x+qv0.w)*r0);
            *(float4*)&ob[(le+1)*64 + m0] =
                make_float4((p0.y+qv1.x)*r1, (p1.y+qv1.y)*r1, (p2.y+qv1.z)*r1, (p3.y+qv1.w)*r1);
        }
    }
}

extern "C" void kernel_launch(void* const* d_in, const int* in_sizes, int n_in,
                              void* d_out, int out_size) {
    const float* q = (const float*)d_in[0];
    const float* k = (const float*)d_in[1];
    const float* v = (const float*)d_in[2];
    float* out = (float*)d_out;

    const int smem = (64*132 + 64*132 + 128*132 + 32 + 2*128*68 + 4*128 + 512) * 4; // 209,024 B
    cudaFuncSetAttribute(fused_cos_attn, cudaFuncAttributeMaxDynamicSharedMemorySize, smem);
    fused_cos_attn<<<NBLK, 512, smem>>>(q, k, v, out);
}